// round 14
// baseline (speedup 1.0000x reference)
#include <cuda_runtime.h>
#include <math.h>
#include <stdint.h>

// ---------------------------------------------------------------------------
// Problem constants
// ---------------------------------------------------------------------------
#define T_STEPS 50
#define BATCH   1024
#define IN_F    784
#define HID     1000
#define OUT_F   100
#define BI      (BATCH*IN_F)           // 802816
#define TOTAL   (T_STEPS*BI)           // 40140800
#define KC      200                    // Eigen aarch64 kc: (16K-384)/80 = 200 (nr=8 NEON gebp)

// ---------------------------------------------------------------------------
// Scratch state (static device globals: no allocation in kernel_launch)
// ---------------------------------------------------------------------------
__device__ float g_X[TOTAL];                      // input spikes (0/1), all steps
__device__ float g_h1m[BATCH*HID];
__device__ float g_h1s[BATCH*HID];
__device__ float g_h2m[BATCH*OUT_F];
__device__ float g_h2s[BATCH*OUT_F];
__device__ float g_dec[3];                        // sigmoid(tau_0), sigmoid(tau_v), sigmoid(acc_tau)

// ---------------------------------------------------------------------------
// Init: decays + state init + zero acc (d_out is poisoned before timing)
// ---------------------------------------------------------------------------
__global__ void k_init(const float* __restrict__ t0, const float* __restrict__ tv,
                       const float* __restrict__ ta, float* __restrict__ out)
{
    int i = blockIdx.x * blockDim.x + threadIdx.x;
    if (i == 0) {
        g_dec[0] = (float)(1.0 / (1.0 + exp(-(double)t0[0])));
        g_dec[1] = (float)(1.0 / (1.0 + exp(-(double)tv[0])));
        g_dec[2] = (float)(1.0 / (1.0 + exp(-(double)ta[0])));
    }
    int stride = gridDim.x * blockDim.x;
    for (int k = i; k < BATCH*HID;   k += stride) { g_h1m[k] = 0.5f; g_h1s[k] = 0.0f; }
    for (int k = i; k < BATCH*OUT_F; k += stride) { g_h2m[k] = 0.5f; g_h2s[k] = 0.0f; }
    for (int k = i; k < BATCH*10;    k += stride) { out[k] = 0.0f; }
}

// ---------------------------------------------------------------------------
// Spike generation: JAX Threefry-2x32, *partitionable* path (confirmed R10).
// key(42) -> (k0,k1)=(0,42). Element e: counter (0, e); out = lane0 ^ lane1.
// uniform = bitcast((bits>>9)|0x3F800000) - 1 ; spike = (u < x[b,j])
// ---------------------------------------------------------------------------
__device__ __forceinline__ unsigned rotl32(unsigned v, int r) {
    return (v << r) | (v >> (32 - r));
}

__global__ void k_spikegen(const float* __restrict__ x)
{
    int e = blockIdx.x * blockDim.x + threadIdx.x;
    if (e >= TOTAL) return;

    const unsigned k0 = 0u, k1 = 42u;
    const unsigned k2 = k0 ^ k1 ^ 0x1BD11BDAu;
    unsigned x0 = 0u + k0;                 // counts_hi + ks[0]
    unsigned x1 = (unsigned)e + k1;        // counts_lo + ks[1]
#define RND(r) x0 += x1; x1 = rotl32(x1,(r)); x1 ^= x0;
    RND(13) RND(15) RND(26) RND(6)   x0 += k1; x1 += k2 + 1u;
    RND(17) RND(29) RND(16) RND(24)  x0 += k2; x1 += k0 + 2u;
    RND(13) RND(15) RND(26) RND(6)   x0 += k0; x1 += k1 + 3u;
    RND(17) RND(29) RND(16) RND(24)  x0 += k1; x1 += k2 + 4u;
    RND(13) RND(15) RND(26) RND(6)   x0 += k2; x1 += k0 + 5u;
#undef RND
    unsigned bits = x0 ^ x1;

    float u = __uint_as_float((bits >> 9) | 0x3F800000u) - 1.0f;
    int r = e % BI;                         // b*784 + j
    g_X[e] = (u < x[r]) ? 1.0f : 0.0f;
}

// ---------------------------------------------------------------------------
// GEMM1 + h1 pPLIF update.
// C[b,n] = sum_k X[t][b][k] * W1[n][k];  M=1024, N=1000, K=784
// 64x64x8 tiles, 128 threads, 8x4 micro-tile, reg-prefetch.
// Accumulation: ascending-k FFMA chains in kc=200 blocks (folds after
// k=200,400,600; tail 184), block partials added ascending — Eigen gebp
// (aarch64 nr=8) blocking of the hypothesized XLA:CPU reference.
// Epilogue: h1m = h1m*dec0*(1-h1s) + C ; h1s = (h1m >= 1)
// ---------------------------------------------------------------------------
#define G1_BM 64
#define G1_BN 64
#define G1_BK 8

__global__ void __launch_bounds__(128) k_gemm1(int t, const float* __restrict__ W1)
{
    __shared__ float As[G1_BK][G1_BM];
    __shared__ float Bs[G1_BK][G1_BN];

    const int tid = threadIdx.x;
    const int m0  = blockIdx.x * G1_BM;
    const int n0  = blockIdx.y * G1_BN;
    const int tx  = tid & 15;        // 16 col-groups of 4
    const int ty  = tid >> 4;        // 8 row-groups of 8
    const int lr  = tid >> 1;        // load row 0..63
    const int lk  = (tid & 1) << 2;  // k offset 0 or 4

    const float* Abase = g_X + (size_t)t * BI + (size_t)(m0 + lr) * IN_F + lk;
    const int    nb    = n0 + lr;
    const bool   bv    = (nb < HID);
    const float* Bbase = W1 + (size_t)(bv ? nb : 0) * IN_F + lk;

    float accT[8][4];   // total (sum of folded kc blocks)
    float accB[8][4];   // current kc-block accumulator
#pragma unroll
    for (int i = 0; i < 8; i++)
#pragma unroll
        for (int j = 0; j < 4; j++) { accT[i][j] = 0.0f; accB[i][j] = 0.0f; }

    float4 aR = *(const float4*)(Abase);
    float4 bR = bv ? *(const float4*)(Bbase) : make_float4(0.f, 0.f, 0.f, 0.f);

    for (int k0 = 0; k0 < IN_F; k0 += G1_BK) {
        As[lk+0][lr] = aR.x; As[lk+1][lr] = aR.y; As[lk+2][lr] = aR.z; As[lk+3][lr] = aR.w;
        Bs[lk+0][lr] = bR.x; Bs[lk+1][lr] = bR.y; Bs[lk+2][lr] = bR.z; Bs[lk+3][lr] = bR.w;
        __syncthreads();

        if (k0 + G1_BK < IN_F) {
            aR = *(const float4*)(Abase + k0 + G1_BK);
            bR = bv ? *(const float4*)(Bbase + k0 + G1_BK) : make_float4(0.f, 0.f, 0.f, 0.f);
        }

#pragma unroll
        for (int kk = 0; kk < G1_BK; kk++) {
            float a[8], b[4];
#pragma unroll
            for (int i = 0; i < 8; i++) a[i] = As[kk][ty*8 + i];
#pragma unroll
            for (int j = 0; j < 4; j++) b[j] = Bs[kk][tx*4 + j];
#pragma unroll
            for (int i = 0; i < 8; i++)
#pragma unroll
                for (int j = 0; j < 4; j++) accB[i][j] += a[i] * b[j];
        }

        // fold at kc-block boundaries (after k reaches 200, 400, 600)
        if (k0 == KC - G1_BK || k0 == 2*KC - G1_BK || k0 == 3*KC - G1_BK) {
#pragma unroll
            for (int i = 0; i < 8; i++)
#pragma unroll
                for (int j = 0; j < 4; j++) {
                    accT[i][j] = __fadd_rn(accT[i][j], accB[i][j]);
                    accB[i][j] = 0.0f;
                }
        }
        __syncthreads();
    }
    // final fold (tail block [600,784))
#pragma unroll
    for (int i = 0; i < 8; i++)
#pragma unroll
        for (int j = 0; j < 4; j++)
            accT[i][j] = __fadd_rn(accT[i][j], accB[i][j]);

    // epilogue: pPLIF update of layer-1 state
    const float dec0 = g_dec[0];
    const int col = n0 + tx * 4;
    if (col < HID) {
#pragma unroll
        for (int i = 0; i < 8; i++) {
            int row = m0 + ty*8 + i;
            int idx = row * HID + col;
            float4 m4 = *(float4*)(g_h1m + idx);
            float4 s4 = *(float4*)(g_h1s + idx);
            float m;
            m = m4.x * dec0 * (1.0f - s4.x) + accT[i][0]; s4.x = (m >= 1.0f) ? 1.0f : 0.0f; m4.x = m;
            m = m4.y * dec0 * (1.0f - s4.y) + accT[i][1]; s4.y = (m >= 1.0f) ? 1.0f : 0.0f; m4.y = m;
            m = m4.z * dec0 * (1.0f - s4.z) + accT[i][2]; s4.z = (m >= 1.0f) ? 1.0f : 0.0f; m4.z = m;
            m = m4.w * dec0 * (1.0f - s4.w) + accT[i][3]; s4.w = (m >= 1.0f) ? 1.0f : 0.0f; m4.w = m;
            *(float4*)(g_h1m + idx) = m4;
            *(float4*)(g_h1s + idx) = s4;
        }
    }
}

// ---------------------------------------------------------------------------
// Fused GEMM2 + h2 pPLIF + avg-pool(10) + pPLI accumulator.
// C[b,o] = sum_{k<1000} h1s[b,k] * W2[o,k], ascending-k chains in kc=200
// blocks (folds after 200,400,600,800 + tail [800,1000)).
// Block: 16 batch rows x all 100 outputs; 400 threads; micro-tile 1x4.
// ---------------------------------------------------------------------------
#define G2_BM 16
#define G2_BK 8
#define G2_T  400

__global__ void __launch_bounds__(512) k_gemm2(const float* __restrict__ W2,
                                               float* __restrict__ out)
{
    __shared__ float As[G2_BK][G2_BM];
    __shared__ float Bs[G2_BK][OUT_F];
    __shared__ float sspk[G2_BM][OUT_F];

    const int tid = threadIdx.x;
    const int m0  = blockIdx.x * G2_BM;
    const int tx  = tid % 25;   // 25 col-groups of 4 -> 100 cols
    const int ty  = tid / 25;   // 16 rows (tid<400)

    float accT[4] = {0.f, 0.f, 0.f, 0.f};
    float accB[4] = {0.f, 0.f, 0.f, 0.f};

    for (int k0 = 0; k0 < HID; k0 += G2_BK) {
        __syncthreads();
        if (tid < G2_BM * G2_BK) {                      // 128 elements
            int r = tid / G2_BK, kk = tid % G2_BK;
            As[kk][r] = g_h1s[(m0 + r) * HID + k0 + kk];
        }
        for (int idx = tid; idx < OUT_F * G2_BK; idx += G2_T) {  // 800 elements
            int o = idx / G2_BK, kk = idx % G2_BK;
            Bs[kk][o] = W2[o * HID + k0 + kk];
        }
        __syncthreads();

#pragma unroll
        for (int kk = 0; kk < G2_BK; kk++) {
            float a = As[kk][ty];
            accB[0] += a * Bs[kk][tx*4+0];
            accB[1] += a * Bs[kk][tx*4+1];
            accB[2] += a * Bs[kk][tx*4+2];
            accB[3] += a * Bs[kk][tx*4+3];
        }

        if (k0 == KC - G2_BK || k0 == 2*KC - G2_BK ||
            k0 == 3*KC - G2_BK || k0 == 4*KC - G2_BK) {
#pragma unroll
            for (int j = 0; j < 4; j++) {
                accT[j] = __fadd_rn(accT[j], accB[j]);
                accB[j] = 0.0f;
            }
        }
    }
#pragma unroll
    for (int j = 0; j < 4; j++)            // tail block [800,1000)
        accT[j] = __fadd_rn(accT[j], accB[j]);

    // h2 pPLIF update
    {
        const float decv = g_dec[1];
        int row = m0 + ty;
        int idx = row * OUT_F + tx * 4;
        float4 m4 = *(float4*)(g_h2m + idx);
        float4 s4 = *(float4*)(g_h2s + idx);
        float m;
        m = m4.x * decv * (1.0f - s4.x) + accT[0]; s4.x = (m >= 1.0f) ? 1.0f : 0.0f; m4.x = m;
        m = m4.y * decv * (1.0f - s4.y) + accT[1]; s4.y = (m >= 1.0f) ? 1.0f : 0.0f; m4.y = m;
        m = m4.z * decv * (1.0f - s4.z) + accT[2]; s4.z = (m >= 1.0f) ? 1.0f : 0.0f; m4.z = m;
        m = m4.w * decv * (1.0f - s4.w) + accT[3]; s4.w = (m >= 1.0f) ? 1.0f : 0.0f; m4.w = m;
        *(float4*)(g_h2m + idx) = m4;
        *(float4*)(g_h2s + idx) = s4;
        sspk[ty][tx*4+0] = s4.x; sspk[ty][tx*4+1] = s4.y;
        sspk[ty][tx*4+2] = s4.z; sspk[ty][tx*4+3] = s4.w;
    }
    __syncthreads();

    // avg-pool(10,10) + leaky accumulator  (sum of 0/1 spikes is exact; /10)
    if (tid < G2_BM * 10) {
        const float deca = g_dec[2];
        int r = tid / 10, o = tid % 10;
        float sum = 0.0f;
#pragma unroll
        for (int i = 0; i < 10; i++) sum = __fadd_rn(sum, sspk[r][o*10 + i]);
        float boost = __fdiv_rn(sum, 10.0f);
        int b = m0 + r;
        out[b*10 + o] = __fadd_rn(__fmul_rn(out[b*10 + o], deca), boost);
    }
}

// ---------------------------------------------------------------------------
// Launch (default stream; graph-capturable: kernels only)
// Inputs (metadata order): x, W1, W2, tau_0, tau_vector, acc_tau
// ---------------------------------------------------------------------------
extern "C" void kernel_launch(void* const* d_in, const int* in_sizes, int n_in,
                              void* d_out, int out_size)
{
    const float* x   = (const float*)d_in[0];
    const float* W1  = (const float*)d_in[1];
    const float* W2  = (const float*)d_in[2];
    const float* t0  = (const float*)d_in[3];
    const float* tv  = (const float*)d_in[4];
    const float* ta  = (const float*)d_in[5];
    float* out = (float*)d_out;
    (void)in_sizes; (void)n_in; (void)out_size;

    k_init<<<256, 256>>>(t0, tv, ta, out);
    k_spikegen<<<(TOTAL + 255) / 256, 256>>>(x);

    dim3 grid1(BATCH / G1_BM, (HID + G1_BN - 1) / G1_BN);  // 16 x 16
    dim3 grid2(BATCH / G2_BM);                             // 64

    for (int t = 0; t < T_STEPS; t++) {
        k_gemm1<<<grid1, 128>>>(t, W1);
        k_gemm2<<<grid2, G2_T>>>(W2, out);
    }
}

// round 15
// speedup vs baseline: 1.8489x; 1.8489x over previous
#include <cuda_runtime.h>
#include <math.h>
#include <stdint.h>

// ---------------------------------------------------------------------------
// Problem constants
// ---------------------------------------------------------------------------
#define T_STEPS 50
#define BATCH   1024
#define IN_F    784
#define HID     1000
#define OUT_F   100
#define BI      (BATCH*IN_F)           // 802816
#define TOTAL   (T_STEPS*BI)           // 40140800
#define KC      200                    // Eigen aarch64 kc (confirmed R14)
#define NSLICE  5                      // GEMM2 k-slices = kc blocks (1000 = 5*200)

// ---------------------------------------------------------------------------
// Scratch state (static device globals)
// ---------------------------------------------------------------------------
__device__ float g_X[TOTAL];
__device__ float g_h1m[BATCH*HID];
__device__ float g_h1s[BATCH*HID];
__device__ float g_h2m[BATCH*OUT_F];
__device__ float g_h2s[BATCH*OUT_F];
__device__ float g_P2[NSLICE*BATCH*OUT_F];   // GEMM2 kc-block partials
__device__ float g_dec[3];

// ---------------------------------------------------------------------------
// Init
// ---------------------------------------------------------------------------
__global__ void k_init(const float* __restrict__ t0, const float* __restrict__ tv,
                       const float* __restrict__ ta, float* __restrict__ out)
{
    int i = blockIdx.x * blockDim.x + threadIdx.x;
    if (i == 0) {
        g_dec[0] = (float)(1.0 / (1.0 + exp(-(double)t0[0])));
        g_dec[1] = (float)(1.0 / (1.0 + exp(-(double)tv[0])));
        g_dec[2] = (float)(1.0 / (1.0 + exp(-(double)ta[0])));
    }
    int stride = gridDim.x * blockDim.x;
    for (int k = i; k < BATCH*HID;   k += stride) { g_h1m[k] = 0.5f; g_h1s[k] = 0.0f; }
    for (int k = i; k < BATCH*OUT_F; k += stride) { g_h2m[k] = 0.5f; g_h2s[k] = 0.0f; }
    for (int k = i; k < BATCH*10;    k += stride) { out[k] = 0.0f; }
}

// ---------------------------------------------------------------------------
// Spike generation: JAX Threefry-2x32 partitionable (confirmed). 4 elems/thread.
// ---------------------------------------------------------------------------
__device__ __forceinline__ unsigned rotl32(unsigned v, int r) {
    return (v << r) | (v >> (32 - r));
}

__device__ __forceinline__ unsigned tf32x(unsigned e)
{
    const unsigned k0 = 0u, k1 = 42u;
    const unsigned k2 = k0 ^ k1 ^ 0x1BD11BDAu;
    unsigned x0 = k0;
    unsigned x1 = e + k1;
#define RND(r) x0 += x1; x1 = rotl32(x1,(r)); x1 ^= x0;
    RND(13) RND(15) RND(26) RND(6)   x0 += k1; x1 += k2 + 1u;
    RND(17) RND(29) RND(16) RND(24)  x0 += k2; x1 += k0 + 2u;
    RND(13) RND(15) RND(26) RND(6)   x0 += k0; x1 += k1 + 3u;
    RND(17) RND(29) RND(16) RND(24)  x0 += k1; x1 += k2 + 4u;
    RND(13) RND(15) RND(26) RND(6)   x0 += k2; x1 += k0 + 5u;
#undef RND
    return x0 ^ x1;
}

__global__ void k_spikegen(const float* __restrict__ x)
{
    int q = blockIdx.x * blockDim.x + threadIdx.x;   // quad index
    int e = q * 4;
    if (e >= TOTAL) return;
    int r = e % BI;                                  // multiple of 4, same row block
    float4 xv = *(const float4*)(x + r);
    float4 ov;
    ov.x = (__uint_as_float((tf32x((unsigned)(e+0)) >> 9) | 0x3F800000u) - 1.0f < xv.x) ? 1.0f : 0.0f;
    ov.y = (__uint_as_float((tf32x((unsigned)(e+1)) >> 9) | 0x3F800000u) - 1.0f < xv.y) ? 1.0f : 0.0f;
    ov.z = (__uint_as_float((tf32x((unsigned)(e+2)) >> 9) | 0x3F800000u) - 1.0f < xv.z) ? 1.0f : 0.0f;
    ov.w = (__uint_as_float((tf32x((unsigned)(e+3)) >> 9) | 0x3F800000u) - 1.0f < xv.w) ? 1.0f : 0.0f;
    *(float4*)(g_X + e) = ov;
}

// ---------------------------------------------------------------------------
// GEMM1 + h1 pPLIF update.  C[b,n] = sum_k X[t][b][k]*W1[n][k]
// 64x64x8 tiles, 128 threads, 8x4 micro-tile, 2-stage smem (1 sync/iter).
// Ascending-k chains, folds after k=200,400,600 (kc=200, confirmed).
// ---------------------------------------------------------------------------
#define G1_BM 64
#define G1_BN 64
#define G1_BK 8
#define G1_NIT (IN_F/G1_BK)   // 98

__global__ void __launch_bounds__(128) k_gemm1(int t, const float* __restrict__ W1)
{
    __shared__ float As[2][G1_BK][G1_BM];
    __shared__ float Bs[2][G1_BK][G1_BN];

    const int tid = threadIdx.x;
    const int m0  = blockIdx.x * G1_BM;
    const int n0  = blockIdx.y * G1_BN;
    const int tx  = tid & 15;
    const int ty  = tid >> 4;
    const int lr  = tid >> 1;
    const int lk  = (tid & 1) << 2;

    const float* Abase = g_X + (size_t)t * BI + (size_t)(m0 + lr) * IN_F + lk;
    const int    nb    = n0 + lr;
    const bool   bv    = (nb < HID);
    const float* Bbase = W1 + (size_t)(bv ? nb : 0) * IN_F + lk;

    float accT[8][4], accB[8][4];
#pragma unroll
    for (int i = 0; i < 8; i++)
#pragma unroll
        for (int j = 0; j < 4; j++) { accT[i][j] = 0.0f; accB[i][j] = 0.0f; }

    // preload tile 0 into stage 0
    {
        float4 aR = *(const float4*)(Abase);
        float4 bR = bv ? *(const float4*)(Bbase) : make_float4(0.f,0.f,0.f,0.f);
        As[0][lk+0][lr]=aR.x; As[0][lk+1][lr]=aR.y; As[0][lk+2][lr]=aR.z; As[0][lk+3][lr]=aR.w;
        Bs[0][lk+0][lr]=bR.x; Bs[0][lk+1][lr]=bR.y; Bs[0][lk+2][lr]=bR.z; Bs[0][lk+3][lr]=bR.w;
    }
    __syncthreads();

    int cur = 0;
    for (int it = 0; it < G1_NIT; it++) {
        const int k0 = it * G1_BK;
        float4 aR, bR;
        const bool more = (it + 1 < G1_NIT);
        if (more) {
            aR = *(const float4*)(Abase + k0 + G1_BK);
            bR = bv ? *(const float4*)(Bbase + k0 + G1_BK) : make_float4(0.f,0.f,0.f,0.f);
        }

#pragma unroll
        for (int kk = 0; kk < G1_BK; kk++) {
            float a[8], b[4];
#pragma unroll
            for (int i = 0; i < 8; i++) a[i] = As[cur][kk][ty*8 + i];
#pragma unroll
            for (int j = 0; j < 4; j++) b[j] = Bs[cur][kk][tx*4 + j];
#pragma unroll
            for (int i = 0; i < 8; i++)
#pragma unroll
                for (int j = 0; j < 4; j++) accB[i][j] += a[i] * b[j];
        }

        if (more) {
            int nxt = cur ^ 1;
            As[nxt][lk+0][lr]=aR.x; As[nxt][lk+1][lr]=aR.y; As[nxt][lk+2][lr]=aR.z; As[nxt][lk+3][lr]=aR.w;
            Bs[nxt][lk+0][lr]=bR.x; Bs[nxt][lk+1][lr]=bR.y; Bs[nxt][lk+2][lr]=bR.z; Bs[nxt][lk+3][lr]=bR.w;
        }

        if (k0 == KC - G1_BK || k0 == 2*KC - G1_BK || k0 == 3*KC - G1_BK) {
#pragma unroll
            for (int i = 0; i < 8; i++)
#pragma unroll
                for (int j = 0; j < 4; j++) {
                    accT[i][j] = __fadd_rn(accT[i][j], accB[i][j]);
                    accB[i][j] = 0.0f;
                }
        }
        __syncthreads();
        cur ^= 1;
    }
#pragma unroll
    for (int i = 0; i < 8; i++)
#pragma unroll
        for (int j = 0; j < 4; j++)
            accT[i][j] = __fadd_rn(accT[i][j], accB[i][j]);

    const float dec0 = g_dec[0];
    const int col = n0 + tx * 4;
    if (col < HID) {
#pragma unroll
        for (int i = 0; i < 8; i++) {
            int row = m0 + ty*8 + i;
            int idx = row * HID + col;
            float4 m4 = *(float4*)(g_h1m + idx);
            float4 s4 = *(float4*)(g_h1s + idx);
            float m;
            m = m4.x * dec0 * (1.0f - s4.x) + accT[i][0]; s4.x = (m >= 1.0f) ? 1.0f : 0.0f; m4.x = m;
            m = m4.y * dec0 * (1.0f - s4.y) + accT[i][1]; s4.y = (m >= 1.0f) ? 1.0f : 0.0f; m4.y = m;
            m = m4.z * dec0 * (1.0f - s4.z) + accT[i][2]; s4.z = (m >= 1.0f) ? 1.0f : 0.0f; m4.z = m;
            m = m4.w * dec0 * (1.0f - s4.w) + accT[i][3]; s4.w = (m >= 1.0f) ? 1.0f : 0.0f; m4.w = m;
            *(float4*)(g_h1m + idx) = m4;
            *(float4*)(g_h1s + idx) = s4;
        }
    }
}

// ---------------------------------------------------------------------------
// GEMM2 kc-block partials (split-K over the LEGAL fold boundaries).
// Block (bx, s): rows [bx*32, bx*32+32), k-slice [200s, 200s+200).
// P2[s][b][o] = ascending-k chain over that slice — bit-identical to the
// per-block chains of the R14-passing kernel; the fold kernel adds them
// in ascending s order (= the confirmed kc=200 fold pattern).
// 128 threads: 100 compute (rg=tid/25 -> 8 rows, oq=tid%25 -> 4 cols).
// ---------------------------------------------------------------------------
#define G2_BM 32
#define G2_BK 40
#define G2_T  128

__global__ void __launch_bounds__(G2_T) k_gemm2(const float* __restrict__ W2)
{
    __shared__ float As[G2_BM][G2_BK];    // [32][40]
    __shared__ float Bs[G2_BK][OUT_F];    // [40][100]

    const int tid   = threadIdx.x;
    const int m0    = blockIdx.x * G2_BM;
    const int s     = blockIdx.y;
    const int kbase = s * KC;
    const int oq    = tid % 25;
    const int rg    = tid / 25;           // 0..3 compute, 4 idle (tid>=100)

    float accB[8][4];
#pragma unroll
    for (int i = 0; i < 8; i++)
#pragma unroll
        for (int j = 0; j < 4; j++) accB[i][j] = 0.0f;

    for (int it = 0; it < KC / G2_BK; it++) {       // 5 sub-tiles of 40
        const int koff = kbase + it * G2_BK;
        __syncthreads();
        // load As: 32 rows x 10 float4
        for (int idx = tid; idx < G2_BM * (G2_BK/4); idx += G2_T) {
            int r = idx / (G2_BK/4), f = idx % (G2_BK/4);
            float4 v = *(const float4*)(g_h1s + (size_t)(m0 + r) * HID + koff + f*4);
            *(float4*)&As[r][f*4] = v;
        }
        // load Bs: 100 o-rows x 10 float4, transposed to [kk][o]
        for (int idx = tid; idx < OUT_F * (G2_BK/4); idx += G2_T) {
            int o = idx / (G2_BK/4), f = idx % (G2_BK/4);
            float4 v = *(const float4*)(W2 + (size_t)o * HID + koff + f*4);
            Bs[f*4+0][o] = v.x; Bs[f*4+1][o] = v.y;
            Bs[f*4+2][o] = v.z; Bs[f*4+3][o] = v.w;
        }
        __syncthreads();

        if (rg < 4) {
#pragma unroll 8
            for (int kk = 0; kk < G2_BK; kk++) {
                float b0 = Bs[kk][oq*4+0], b1 = Bs[kk][oq*4+1];
                float b2 = Bs[kk][oq*4+2], b3 = Bs[kk][oq*4+3];
#pragma unroll
                for (int i = 0; i < 8; i++) {
                    float a = As[rg*8 + i][kk];
                    accB[i][0] += a * b0; accB[i][1] += a * b1;
                    accB[i][2] += a * b2; accB[i][3] += a * b3;
                }
            }
        }
    }

    if (rg < 4) {
        float* P = g_P2 + (size_t)s * BATCH * OUT_F;
#pragma unroll
        for (int i = 0; i < 8; i++) {
            int row = m0 + rg*8 + i;
            float4 v = make_float4(accB[i][0], accB[i][1], accB[i][2], accB[i][3]);
            *(float4*)(P + (size_t)row * OUT_F + oq*4) = v;
        }
    }
}

// ---------------------------------------------------------------------------
// Fold partials (ascending slice order = kc=200 folds) + h2 pPLIF +
// avg-pool(10) + pPLI accumulator.  128 blocks x 8 rows.
// ---------------------------------------------------------------------------
__global__ void __launch_bounds__(128) k_h2pool(float* __restrict__ out)
{
    __shared__ float sspk[8][OUT_F];
    const int b0 = blockIdx.x * 8;
    const int tid = threadIdx.x;
    const float decv = g_dec[1];
    const float deca = g_dec[2];

    if (tid < OUT_F) {
        const int o = tid;
#pragma unroll
        for (int r = 0; r < 8; r++) {
            int b = b0 + r;
            int idx = b * OUT_F + o;
            float I = g_P2[0*BATCH*OUT_F + idx];
            I = __fadd_rn(I, g_P2[1*BATCH*OUT_F + idx]);
            I = __fadd_rn(I, g_P2[2*BATCH*OUT_F + idx]);
            I = __fadd_rn(I, g_P2[3*BATCH*OUT_F + idx]);
            I = __fadd_rn(I, g_P2[4*BATCH*OUT_F + idx]);
            float m = g_h2m[idx] * decv * (1.0f - g_h2s[idx]) + I;
            float spk = (m >= 1.0f) ? 1.0f : 0.0f;
            g_h2m[idx] = m;
            g_h2s[idx] = spk;
            sspk[r][o] = spk;
        }
    }
    __syncthreads();
    if (tid < 80) {
        int r = tid / 10, o = tid % 10;
        float sum = 0.0f;
#pragma unroll
        for (int i = 0; i < 10; i++) sum = __fadd_rn(sum, sspk[r][o*10 + i]);
        float boost = __fdiv_rn(sum, 10.0f);
        int b = b0 + r;
        out[b*10 + o] = __fadd_rn(__fmul_rn(out[b*10 + o], deca), boost);
    }
}

// ---------------------------------------------------------------------------
// Launch
// ---------------------------------------------------------------------------
extern "C" void kernel_launch(void* const* d_in, const int* in_sizes, int n_in,
                              void* d_out, int out_size)
{
    const float* x   = (const float*)d_in[0];
    const float* W1  = (const float*)d_in[1];
    const float* W2  = (const float*)d_in[2];
    const float* t0  = (const float*)d_in[3];
    const float* tv  = (const float*)d_in[4];
    const float* ta  = (const float*)d_in[5];
    float* out = (float*)d_out;
    (void)in_sizes; (void)n_in; (void)out_size;

    k_init<<<256, 256>>>(t0, tv, ta, out);
    k_spikegen<<<(TOTAL/4 + 255) / 256, 256>>>(x);

    dim3 grid1(BATCH / G1_BM, (HID + G1_BN - 1) / G1_BN);  // 16 x 16
    dim3 grid2(BATCH / G2_BM, NSLICE);                     // 32 x 5

    for (int t = 0; t < T_STEPS; t++) {
        k_gemm1<<<grid1, 128>>>(t, W1);
        k_gemm2<<<grid2, G2_T>>>(W2);
        k_h2pool<<<BATCH/8, 128>>>(out);
    }
}

// round 16
// speedup vs baseline: 2.3897x; 1.2925x over previous
#include <cuda_runtime.h>
#include <math.h>
#include <stdint.h>

// ---------------------------------------------------------------------------
// Problem constants
// ---------------------------------------------------------------------------
#define T_STEPS 50
#define BATCH   1024
#define IN_F    784
#define HID     1000
#define OUT_F   100
#define BI      (BATCH*IN_F)           // 802816
#define TOTAL   (T_STEPS*BI)           // 40140800
#define KC      200                    // Eigen aarch64 kc (confirmed R14)
#define NSLICE  5                      // 1000 = 5 * 200
#define BO      (BATCH*OUT_F)

// ---------------------------------------------------------------------------
// Scratch state (static device globals)
// ---------------------------------------------------------------------------
__device__ __align__(16) float g_X[TOTAL];
__device__ __align__(16) float g_h1m[BATCH*HID];
__device__ __align__(16) float g_h1s2[2*BATCH*HID];   // double-buffered spikes
__device__ __align__(16) float g_h2m[BO];
__device__ __align__(16) float g_h2s[BO];
__device__ __align__(16) float g_P2[NSLICE*BO];       // GEMM2 kc-block partials
__device__ float g_dec[3];
__device__ unsigned g_cnt[32];                        // per-m-tile fold counters

// ---------------------------------------------------------------------------
// Init
// ---------------------------------------------------------------------------
__global__ void k_init(const float* __restrict__ t0, const float* __restrict__ tv,
                       const float* __restrict__ ta, float* __restrict__ out)
{
    int i = blockIdx.x * blockDim.x + threadIdx.x;
    if (i == 0) {
        g_dec[0] = (float)(1.0 / (1.0 + exp(-(double)t0[0])));
        g_dec[1] = (float)(1.0 / (1.0 + exp(-(double)tv[0])));
        g_dec[2] = (float)(1.0 / (1.0 + exp(-(double)ta[0])));
    }
    int stride = gridDim.x * blockDim.x;
    for (int k = i; k < BATCH*HID;   k += stride) g_h1m[k] = 0.5f;
    for (int k = i; k < 2*BATCH*HID; k += stride) g_h1s2[k] = 0.0f;
    for (int k = i; k < BO;          k += stride) { g_h2m[k] = 0.5f; g_h2s[k] = 0.0f; }
    for (int k = i; k < BATCH*10;    k += stride) out[k] = 0.0f;
    if (i < 32) g_cnt[i] = 0u;
}

// ---------------------------------------------------------------------------
// Spike generation: JAX Threefry-2x32 partitionable (confirmed R10/R14).
// ---------------------------------------------------------------------------
__device__ __forceinline__ unsigned rotl32(unsigned v, int r) {
    return (v << r) | (v >> (32 - r));
}

__device__ __forceinline__ unsigned tf32x(unsigned e)
{
    const unsigned k0 = 0u, k1 = 42u;
    const unsigned k2 = k0 ^ k1 ^ 0x1BD11BDAu;
    unsigned x0 = k0;
    unsigned x1 = e + k1;
#define RND(r) x0 += x1; x1 = rotl32(x1,(r)); x1 ^= x0;
    RND(13) RND(15) RND(26) RND(6)   x0 += k1; x1 += k2 + 1u;
    RND(17) RND(29) RND(16) RND(24)  x0 += k2; x1 += k0 + 2u;
    RND(13) RND(15) RND(26) RND(6)   x0 += k0; x1 += k1 + 3u;
    RND(17) RND(29) RND(16) RND(24)  x0 += k1; x1 += k2 + 4u;
    RND(13) RND(15) RND(26) RND(6)   x0 += k2; x1 += k0 + 5u;
#undef RND
    return x0 ^ x1;
}

__global__ void k_spikegen(const float* __restrict__ x)
{
    int q = blockIdx.x * blockDim.x + threadIdx.x;
    int e = q * 4;
    if (e >= TOTAL) return;
    int r = e % BI;
    float4 xv = *(const float4*)(x + r);
    float4 ov;
    ov.x = (__uint_as_float((tf32x((unsigned)(e+0)) >> 9) | 0x3F800000u) - 1.0f < xv.x) ? 1.0f : 0.0f;
    ov.y = (__uint_as_float((tf32x((unsigned)(e+1)) >> 9) | 0x3F800000u) - 1.0f < xv.y) ? 1.0f : 0.0f;
    ov.z = (__uint_as_float((tf32x((unsigned)(e+2)) >> 9) | 0x3F800000u) - 1.0f < xv.z) ? 1.0f : 0.0f;
    ov.w = (__uint_as_float((tf32x((unsigned)(e+3)) >> 9) | 0x3F800000u) - 1.0f < xv.w) ? 1.0f : 0.0f;
    *(float4*)(g_X + e) = ov;
}

// ---------------------------------------------------------------------------
// Shared-memory union (per block): max of gemm1 (8KB), gemm2 (21.1KB),
// fold sspk (12.8KB)
// ---------------------------------------------------------------------------
#define SMEM_FLOATS 5280   // 21120 bytes

// ---------------------------------------------------------------------------
// GEMM1 body (identical arithmetic to R14/R15-pass kernel).
// 64x64x8 tiles, 128 threads, 8x4 micro-tile, 2-stage smem.
// kc=200 folds after k=200,400,600; tail 184.
// ---------------------------------------------------------------------------
#define G1_BM 64
#define G1_BN 64
#define G1_BK 8
#define G1_NIT (IN_F/G1_BK)   // 98

__device__ __forceinline__ void gemm1_body(int t, const float* __restrict__ W1,
                                           float* sm, int bx, int by)
{
    float (*As)[G1_BK][G1_BM] = (float (*)[G1_BK][G1_BM])sm;
    float (*Bs)[G1_BK][G1_BN] = (float (*)[G1_BK][G1_BN])(sm + 2*G1_BK*G1_BM);

    const float* sOld = g_h1s2 + (size_t)((t+1)&1) * (BATCH*HID);
    float*       sNew = g_h1s2 + (size_t)(t&1)     * (BATCH*HID);

    const int tid = threadIdx.x;
    const int m0  = bx * G1_BM;
    const int n0  = by * G1_BN;
    const int tx  = tid & 15;
    const int ty  = tid >> 4;
    const int lr  = tid >> 1;
    const int lk  = (tid & 1) << 2;

    const float* Abase = g_X + (size_t)t * BI + (size_t)(m0 + lr) * IN_F + lk;
    const int    nb    = n0 + lr;
    const bool   bv    = (nb < HID);
    const float* Bbase = W1 + (size_t)(bv ? nb : 0) * IN_F + lk;

    float accT[8][4], accB[8][4];
#pragma unroll
    for (int i = 0; i < 8; i++)
#pragma unroll
        for (int j = 0; j < 4; j++) { accT[i][j] = 0.0f; accB[i][j] = 0.0f; }

    {
        float4 aR = *(const float4*)(Abase);
        float4 bR = bv ? *(const float4*)(Bbase) : make_float4(0.f,0.f,0.f,0.f);
        As[0][lk+0][lr]=aR.x; As[0][lk+1][lr]=aR.y; As[0][lk+2][lr]=aR.z; As[0][lk+3][lr]=aR.w;
        Bs[0][lk+0][lr]=bR.x; Bs[0][lk+1][lr]=bR.y; Bs[0][lk+2][lr]=bR.z; Bs[0][lk+3][lr]=bR.w;
    }
    __syncthreads();

    int cur = 0;
    for (int it = 0; it < G1_NIT; it++) {
        const int k0 = it * G1_BK;
        float4 aR, bR;
        const bool more = (it + 1 < G1_NIT);
        if (more) {
            aR = *(const float4*)(Abase + k0 + G1_BK);
            bR = bv ? *(const float4*)(Bbase + k0 + G1_BK) : make_float4(0.f,0.f,0.f,0.f);
        }

#pragma unroll
        for (int kk = 0; kk < G1_BK; kk++) {
            float a[8], b[4];
#pragma unroll
            for (int i = 0; i < 8; i++) a[i] = As[cur][kk][ty*8 + i];
#pragma unroll
            for (int j = 0; j < 4; j++) b[j] = Bs[cur][kk][tx*4 + j];
#pragma unroll
            for (int i = 0; i < 8; i++)
#pragma unroll
                for (int j = 0; j < 4; j++) accB[i][j] += a[i] * b[j];
        }

        if (more) {
            int nxt = cur ^ 1;
            As[nxt][lk+0][lr]=aR.x; As[nxt][lk+1][lr]=aR.y; As[nxt][lk+2][lr]=aR.z; As[nxt][lk+3][lr]=aR.w;
            Bs[nxt][lk+0][lr]=bR.x; Bs[nxt][lk+1][lr]=bR.y; Bs[nxt][lk+2][lr]=bR.z; Bs[nxt][lk+3][lr]=bR.w;
        }

        if (k0 == KC - G1_BK || k0 == 2*KC - G1_BK || k0 == 3*KC - G1_BK) {
#pragma unroll
            for (int i = 0; i < 8; i++)
#pragma unroll
                for (int j = 0; j < 4; j++) {
                    accT[i][j] = __fadd_rn(accT[i][j], accB[i][j]);
                    accB[i][j] = 0.0f;
                }
        }
        __syncthreads();
        cur ^= 1;
    }
#pragma unroll
    for (int i = 0; i < 8; i++)
#pragma unroll
        for (int j = 0; j < 4; j++)
            accT[i][j] = __fadd_rn(accT[i][j], accB[i][j]);

    const float dec0 = g_dec[0];
    const int col = n0 + tx * 4;
    if (col < HID) {
#pragma unroll
        for (int i = 0; i < 8; i++) {
            int row = m0 + ty*8 + i;
            int idx = row * HID + col;
            float4 m4 = *(float4*)(g_h1m + idx);
            float4 s4 = *(const float4*)(sOld + idx);
            float m;
            m = m4.x * dec0 * (1.0f - s4.x) + accT[i][0]; s4.x = (m >= 1.0f) ? 1.0f : 0.0f; m4.x = m;
            m = m4.y * dec0 * (1.0f - s4.y) + accT[i][1]; s4.y = (m >= 1.0f) ? 1.0f : 0.0f; m4.y = m;
            m = m4.z * dec0 * (1.0f - s4.z) + accT[i][2]; s4.z = (m >= 1.0f) ? 1.0f : 0.0f; m4.z = m;
            m = m4.w * dec0 * (1.0f - s4.w) + accT[i][3]; s4.w = (m >= 1.0f) ? 1.0f : 0.0f; m4.w = m;
            *(float4*)(g_h1m + idx) = m4;
            *(float4*)(sNew + idx)  = s4;
        }
    }
}

// ---------------------------------------------------------------------------
// GEMM2 + fused fold body for step u.
// Block (mt, s): rows [mt*32, mt*32+32), k-slice [200s, 200s+200).
// Transposed As[kk][32] -> a loads are 2x LDS.128. 100 compute threads,
// 8 rows x 4 cols each. Partials written to g_P2; last-arriving block per
// m-tile folds slices (ascending order = confirmed kc=200 pattern),
// does h2 pPLIF + avg-pool + accumulator.
// ---------------------------------------------------------------------------
#define G2_BM 32
#define G2_BK 40

__device__ __forceinline__ void gemm2_fold_body(int u, const float* __restrict__ W2,
                                                float* __restrict__ out,
                                                float* sm, int mt, int s,
                                                unsigned* s_last)
{
    float* As = sm;                 // [G2_BK][32]
    float* Bs = sm + G2_BK*G2_BM;   // [G2_BK][100]

    const float* h1sOld = g_h1s2 + (size_t)(u&1) * (BATCH*HID);

    const int tid   = threadIdx.x;
    const int m0    = mt * G2_BM;
    const int kbase = s * KC;
    const int oq    = tid % 25;
    const int rg    = tid / 25;     // 0..3 compute; 4,5 idle for compute

    float accB[8][4];
#pragma unroll
    for (int i = 0; i < 8; i++)
#pragma unroll
        for (int j = 0; j < 4; j++) accB[i][j] = 0.0f;

    for (int sub = 0; sub < KC / G2_BK; sub++) {
        const int koff = kbase + sub * G2_BK;
        __syncthreads();
        // As fill: 32 rows x 40 k, transposed to [kk][r]
        for (int idx = tid; idx < G2_BM * (G2_BK/4); idx += 128) {
            int r = idx / (G2_BK/4), f = idx % (G2_BK/4);
            float4 v = *(const float4*)(h1sOld + (size_t)(m0 + r) * HID + koff + f*4);
            As[(f*4+0)*G2_BM + r] = v.x; As[(f*4+1)*G2_BM + r] = v.y;
            As[(f*4+2)*G2_BM + r] = v.z; As[(f*4+3)*G2_BM + r] = v.w;
        }
        // Bs fill: 100 o x 40 k, transposed to [kk][o]
        for (int idx = tid; idx < OUT_F * (G2_BK/4); idx += 128) {
            int o = idx / (G2_BK/4), f = idx % (G2_BK/4);
            float4 v = *(const float4*)(W2 + (size_t)o * HID + koff + f*4);
            Bs[(f*4+0)*OUT_F + o] = v.x; Bs[(f*4+1)*OUT_F + o] = v.y;
            Bs[(f*4+2)*OUT_F + o] = v.z; Bs[(f*4+3)*OUT_F + o] = v.w;
        }
        __syncthreads();

        if (rg < 4) {
#pragma unroll 8
            for (int kk = 0; kk < G2_BK; kk++) {
                float4 a0 = *(float4*)&As[kk*G2_BM + rg*8];
                float4 a1 = *(float4*)&As[kk*G2_BM + rg*8 + 4];
                float4 b  = *(float4*)&Bs[kk*OUT_F + oq*4];
                float a[8] = {a0.x,a0.y,a0.z,a0.w,a1.x,a1.y,a1.z,a1.w};
#pragma unroll
                for (int i = 0; i < 8; i++) {
                    accB[i][0] += a[i] * b.x; accB[i][1] += a[i] * b.y;
                    accB[i][2] += a[i] * b.z; accB[i][3] += a[i] * b.w;
                }
            }
        }
    }

    if (rg < 4) {
        float* P = g_P2 + (size_t)s * BO;
#pragma unroll
        for (int i = 0; i < 8; i++) {
            int row = m0 + rg*8 + i;
            float4 v = make_float4(accB[i][0], accB[i][1], accB[i][2], accB[i][3]);
            *(float4*)(P + (size_t)row * OUT_F + oq*4) = v;
        }
    }

    // --- fold: last-arriving block for this m-tile ---
    __threadfence();
    if (tid == 0) *s_last = (atomicAdd(&g_cnt[mt], 1u) == NSLICE - 1) ? 1u : 0u;
    __syncthreads();
    if (!*s_last) return;
    if (tid == 0) g_cnt[mt] = 0u;
    __threadfence();   // acquire: see all P2 writes
    __syncthreads();   // smem reuse safety

    float* sspk = sm;  // [32][100]
    const float decv = g_dec[1];
    const float deca = g_dec[2];

    if (tid < OUT_F) {
        const int o = tid;
        for (int r = 0; r < G2_BM; r++) {
            int idx = (m0 + r) * OUT_F + o;
            float I = g_P2[idx];
            I = __fadd_rn(I, g_P2[1*BO + idx]);
            I = __fadd_rn(I, g_P2[2*BO + idx]);
            I = __fadd_rn(I, g_P2[3*BO + idx]);
            I = __fadd_rn(I, g_P2[4*BO + idx]);
            float m = g_h2m[idx] * decv * (1.0f - g_h2s[idx]) + I;
            float spk = (m >= 1.0f) ? 1.0f : 0.0f;
            g_h2m[idx] = m;
            g_h2s[idx] = spk;
            sspk[r*OUT_F + o] = spk;
        }
    }
    __syncthreads();
    for (int idx = tid; idx < G2_BM * 10; idx += 128) {
        int r = idx / 10, o = idx % 10;
        float sum = 0.0f;
#pragma unroll
        for (int i = 0; i < 10; i++) sum = __fadd_rn(sum, sspk[r*OUT_F + o*10 + i]);
        float boost = __fdiv_rn(sum, 10.0f);
        int b = m0 + r;
        out[b*10 + o] = __fadd_rn(__fmul_rn(out[b*10 + o], deca), boost);
    }
}

// ---------------------------------------------------------------------------
// Combined per-step kernel: blocks [0,256) = gemm1(t); [256,416) = gemm2(t-1)+fold
// ---------------------------------------------------------------------------
#define G1_BLOCKS 256
#define G2_BLOCKS 160

__global__ void __launch_bounds__(128) k_step(int t, const float* __restrict__ W1,
                                              const float* __restrict__ W2,
                                              float* __restrict__ out)
{
    __shared__ __align__(16) float sm[SMEM_FLOATS];
    __shared__ unsigned s_last;
    int bid = blockIdx.x;
    if (bid < G1_BLOCKS) {
        gemm1_body(t, W1, sm, bid & 15, bid >> 4);
    } else if (t > 0) {
        int g = bid - G1_BLOCKS;
        gemm2_fold_body(t - 1, W2, out, sm, g % 32, g / 32, &s_last);
    }
}

// Tail: gemm2+fold for the final step
__global__ void __launch_bounds__(128) k_tail(const float* __restrict__ W2,
                                              float* __restrict__ out)
{
    __shared__ __align__(16) float sm[SMEM_FLOATS];
    __shared__ unsigned s_last;
    int g = blockIdx.x;
    gemm2_fold_body(T_STEPS - 1, W2, out, sm, g % 32, g / 32, &s_last);
}

// ---------------------------------------------------------------------------
// Launch
// ---------------------------------------------------------------------------
extern "C" void kernel_launch(void* const* d_in, const int* in_sizes, int n_in,
                              void* d_out, int out_size)
{
    const float* x   = (const float*)d_in[0];
    const float* W1  = (const float*)d_in[1];
    const float* W2  = (const float*)d_in[2];
    const float* t0  = (const float*)d_in[3];
    const float* tv  = (const float*)d_in[4];
    const float* ta  = (const float*)d_in[5];
    float* out = (float*)d_out;
    (void)in_sizes; (void)n_in; (void)out_size;

    k_init<<<256, 256>>>(t0, tv, ta, out);
    k_spikegen<<<(TOTAL/4 + 255) / 256, 256>>>(x);

    for (int t = 0; t < T_STEPS; t++)
        k_step<<<G1_BLOCKS + G2_BLOCKS, 128>>>(t, W1, W2, out);
    k_tail<<<G2_BLOCKS, 128>>>(W2, out);
}

// round 17
// speedup vs baseline: 2.5496x; 1.0669x over previous
#include <cuda_runtime.h>
#include <math.h>
#include <stdint.h>

// ---------------------------------------------------------------------------
// Problem constants
// ---------------------------------------------------------------------------
#define T_STEPS 50
#define BATCH   1024
#define IN_F    784
#define HID     1000
#define OUT_F   100
#define BI      (BATCH*IN_F)           // 802816
#define TOTAL   (T_STEPS*BI)           // 40140800
#define KC      200                    // Eigen aarch64 kc (confirmed R14)
#define NSLICE  5                      // gemm2: 1000 = 5*200
#define NS1     4                      // gemm1: 784 = 200+200+200+184
#define BO      (BATCH*OUT_F)
#define G1_TILES 256                   // 16 x 16 tiles of 64x64

// ---------------------------------------------------------------------------
// Scratch state (static device globals)
// ---------------------------------------------------------------------------
__device__ __align__(16) float g_X[TOTAL];
__device__ __align__(16) float g_h1m[BATCH*HID];
__device__ __align__(16) float g_h1s2[2*BATCH*HID];   // double-buffered spikes
__device__ __align__(16) float g_h2m[BO];
__device__ __align__(16) float g_h2s[BO];
__device__ __align__(16) float g_P1[NS1*G1_TILES*4096];  // gemm1 kc-slice partials (16.8MB)
__device__ __align__(16) float g_P2[NSLICE*BO];          // gemm2 kc-slice partials
__device__ float g_dec[3];
__device__ unsigned g_cnt1[G1_TILES];
__device__ unsigned g_cnt2[32];

// ---------------------------------------------------------------------------
// Init
// ---------------------------------------------------------------------------
__global__ void k_init(const float* __restrict__ t0, const float* __restrict__ tv,
                       const float* __restrict__ ta, float* __restrict__ out)
{
    int i = blockIdx.x * blockDim.x + threadIdx.x;
    if (i == 0) {
        g_dec[0] = (float)(1.0 / (1.0 + exp(-(double)t0[0])));
        g_dec[1] = (float)(1.0 / (1.0 + exp(-(double)tv[0])));
        g_dec[2] = (float)(1.0 / (1.0 + exp(-(double)ta[0])));
    }
    int stride = gridDim.x * blockDim.x;
    for (int k = i; k < BATCH*HID;   k += stride) g_h1m[k] = 0.5f;
    for (int k = i; k < 2*BATCH*HID; k += stride) g_h1s2[k] = 0.0f;
    for (int k = i; k < BO;          k += stride) { g_h2m[k] = 0.5f; g_h2s[k] = 0.0f; }
    for (int k = i; k < BATCH*10;    k += stride) out[k] = 0.0f;
    if (i < G1_TILES) g_cnt1[i] = 0u;
    if (i < 32)       g_cnt2[i] = 0u;
}

// ---------------------------------------------------------------------------
// Spike generation: JAX Threefry-2x32 partitionable (confirmed R10/R14).
// ---------------------------------------------------------------------------
__device__ __forceinline__ unsigned rotl32(unsigned v, int r) {
    return (v << r) | (v >> (32 - r));
}

__device__ __forceinline__ unsigned tf32x(unsigned e)
{
    const unsigned k0 = 0u, k1 = 42u;
    const unsigned k2 = k0 ^ k1 ^ 0x1BD11BDAu;
    unsigned x0 = k0;
    unsigned x1 = e + k1;
#define RND(r) x0 += x1; x1 = rotl32(x1,(r)); x1 ^= x0;
    RND(13) RND(15) RND(26) RND(6)   x0 += k1; x1 += k2 + 1u;
    RND(17) RND(29) RND(16) RND(24)  x0 += k2; x1 += k0 + 2u;
    RND(13) RND(15) RND(26) RND(6)   x0 += k0; x1 += k1 + 3u;
    RND(17) RND(29) RND(16) RND(24)  x0 += k1; x1 += k2 + 4u;
    RND(13) RND(15) RND(26) RND(6)   x0 += k2; x1 += k0 + 5u;
#undef RND
    return x0 ^ x1;
}

__global__ void k_spikegen(const float* __restrict__ x)
{
    int q = blockIdx.x * blockDim.x + threadIdx.x;
    int e = q * 4;
    if (e >= TOTAL) return;
    int r = e % BI;
    float4 xv = *(const float4*)(x + r);
    float4 ov;
    ov.x = (__uint_as_float((tf32x((unsigned)(e+0)) >> 9) | 0x3F800000u) - 1.0f < xv.x) ? 1.0f : 0.0f;
    ov.y = (__uint_as_float((tf32x((unsigned)(e+1)) >> 9) | 0x3F800000u) - 1.0f < xv.y) ? 1.0f : 0.0f;
    ov.z = (__uint_as_float((tf32x((unsigned)(e+2)) >> 9) | 0x3F800000u) - 1.0f < xv.z) ? 1.0f : 0.0f;
    ov.w = (__uint_as_float((tf32x((unsigned)(e+3)) >> 9) | 0x3F800000u) - 1.0f < xv.w) ? 1.0f : 0.0f;
    *(float4*)(g_X + e) = ov;
}

// ---------------------------------------------------------------------------
// Shared memory union: gemm1 slice 2048 floats; gemm2 2640; fold sspk 3200.
// ---------------------------------------------------------------------------
#define SMEM_FLOATS 3200   // 12.8 KB

// ---------------------------------------------------------------------------
// GEMM1 kc-slice body. Block (bx,by,s): tile rows [bx*64,+64), cols [by*64,+64),
// k in [200s, min(200s+200,784)). Ascending-k chain over the slice — identical
// arithmetic to the monolithic kernel's per-block chain (G1_BK=8 subchunks).
// Last-arriving of the 4 slices folds ascending (= confirmed kc=200 pattern)
// and runs the h1 pPLIF epilogue.
// ---------------------------------------------------------------------------
#define G1_BM 64
#define G1_BN 64
#define G1_BK 8

__device__ __forceinline__ void gemm1_slice_body(int t, const float* __restrict__ W1,
                                                 float* sm, int bx, int by, int s,
                                                 unsigned* s_last)
{
    float (*As)[G1_BK][G1_BM] = (float (*)[G1_BK][G1_BM])sm;
    float (*Bs)[G1_BK][G1_BN] = (float (*)[G1_BK][G1_BN])(sm + 2*G1_BK*G1_BM);

    const int tid = threadIdx.x;
    const int m0  = bx * G1_BM;
    const int n0  = by * G1_BN;
    const int tx  = tid & 15;
    const int ty  = tid >> 4;
    const int lr  = tid >> 1;
    const int lk  = (tid & 1) << 2;

    const int kbase = s * KC;
    const int nit   = (s < 3) ? (KC/G1_BK) : ((IN_F - 3*KC)/G1_BK);   // 25 or 23

    const float* Abase = g_X + (size_t)t * BI + (size_t)(m0 + lr) * IN_F + kbase + lk;
    const int    nb    = n0 + lr;
    const bool   bv    = (nb < HID);
    const float* Bbase = W1 + (size_t)(bv ? nb : 0) * IN_F + kbase + lk;

    float accB[8][4];
#pragma unroll
    for (int i = 0; i < 8; i++)
#pragma unroll
        for (int j = 0; j < 4; j++) accB[i][j] = 0.0f;

    {
        float4 aR = *(const float4*)(Abase);
        float4 bR = bv ? *(const float4*)(Bbase) : make_float4(0.f,0.f,0.f,0.f);
        As[0][lk+0][lr]=aR.x; As[0][lk+1][lr]=aR.y; As[0][lk+2][lr]=aR.z; As[0][lk+3][lr]=aR.w;
        Bs[0][lk+0][lr]=bR.x; Bs[0][lk+1][lr]=bR.y; Bs[0][lk+2][lr]=bR.z; Bs[0][lk+3][lr]=bR.w;
    }
    __syncthreads();

    int cur = 0;
    for (int it = 0; it < nit; it++) {
        const int k0 = it * G1_BK;
        float4 aR, bR;
        const bool more = (it + 1 < nit);
        if (more) {
            aR = *(const float4*)(Abase + k0 + G1_BK);
            bR = bv ? *(const float4*)(Bbase + k0 + G1_BK) : make_float4(0.f,0.f,0.f,0.f);
        }

#pragma unroll
        for (int kk = 0; kk < G1_BK; kk++) {
            float a[8], b[4];
#pragma unroll
            for (int i = 0; i < 8; i++) a[i] = As[cur][kk][ty*8 + i];
#pragma unroll
            for (int j = 0; j < 4; j++) b[j] = Bs[cur][kk][tx*4 + j];
#pragma unroll
            for (int i = 0; i < 8; i++)
#pragma unroll
                for (int j = 0; j < 4; j++) accB[i][j] += a[i] * b[j];
        }

        if (more) {
            int nxt = cur ^ 1;
            As[nxt][lk+0][lr]=aR.x; As[nxt][lk+1][lr]=aR.y; As[nxt][lk+2][lr]=aR.z; As[nxt][lk+3][lr]=aR.w;
            Bs[nxt][lk+0][lr]=bR.x; Bs[nxt][lk+1][lr]=bR.y; Bs[nxt][lk+2][lr]=bR.z; Bs[nxt][lk+3][lr]=bR.w;
        }
        __syncthreads();
        cur ^= 1;
    }

    // write slice partial
    const int tile = by * 16 + bx;
    {
        float* P = g_P1 + ((size_t)s * G1_TILES + tile) * 4096;
#pragma unroll
        for (int i = 0; i < 8; i++) {
            int l = ty*8 + i;
            float4 v = make_float4(accB[i][0], accB[i][1], accB[i][2], accB[i][3]);
            *(float4*)(P + l*64 + tx*4) = v;
        }
    }

    // last-arriving slice folds + epilogue
    __threadfence();
    if (tid == 0) *s_last = (atomicAdd(&g_cnt1[tile], 1u) == NS1 - 1) ? 1u : 0u;
    __syncthreads();
    if (!*s_last) return;
    if (tid == 0) g_cnt1[tile] = 0u;
    __threadfence();

    const float* sOld = g_h1s2 + (size_t)((t+1)&1) * (BATCH*HID);
    float*       sNew = g_h1s2 + (size_t)(t&1)     * (BATCH*HID);
    const float dec0 = g_dec[0];
    const int col = n0 + tx * 4;
    if (col < HID) {
        const float* P0 = g_P1 + ((size_t)0 * G1_TILES + tile) * 4096;
        const float* P1 = g_P1 + ((size_t)1 * G1_TILES + tile) * 4096;
        const float* P2 = g_P1 + ((size_t)2 * G1_TILES + tile) * 4096;
        const float* P3 = g_P1 + ((size_t)3 * G1_TILES + tile) * 4096;
#pragma unroll
        for (int i = 0; i < 8; i++) {
            int l = ty*8 + i;
            int off = l*64 + tx*4;
            float4 v0 = *(const float4*)(P0 + off);
            float4 v1 = *(const float4*)(P1 + off);
            float4 v2 = *(const float4*)(P2 + off);
            float4 v3 = *(const float4*)(P3 + off);
            float4 c;
            c.x = __fadd_rn(__fadd_rn(__fadd_rn(v0.x, v1.x), v2.x), v3.x);
            c.y = __fadd_rn(__fadd_rn(__fadd_rn(v0.y, v1.y), v2.y), v3.y);
            c.z = __fadd_rn(__fadd_rn(__fadd_rn(v0.z, v1.z), v2.z), v3.z);
            c.w = __fadd_rn(__fadd_rn(__fadd_rn(v0.w, v1.w), v2.w), v3.w);

            int row = m0 + l;
            int idx = row * HID + col;
            float4 m4 = *(float4*)(g_h1m + idx);
            float4 s4 = *(const float4*)(sOld + idx);
            float m;
            m = m4.x * dec0 * (1.0f - s4.x) + c.x; s4.x = (m >= 1.0f) ? 1.0f : 0.0f; m4.x = m;
            m = m4.y * dec0 * (1.0f - s4.y) + c.y; s4.y = (m >= 1.0f) ? 1.0f : 0.0f; m4.y = m;
            m = m4.z * dec0 * (1.0f - s4.z) + c.z; s4.z = (m >= 1.0f) ? 1.0f : 0.0f; m4.z = m;
            m = m4.w * dec0 * (1.0f - s4.w) + c.w; s4.w = (m >= 1.0f) ? 1.0f : 0.0f; m4.w = m;
            *(float4*)(g_h1m + idx) = m4;
            *(float4*)(sNew + idx)  = s4;
        }
    }
}

// ---------------------------------------------------------------------------
// GEMM2 kc-slice + fused fold body for step u (arithmetic identical to R16).
// G2_BK reduced 40->20 to shrink smem (residency).
// ---------------------------------------------------------------------------
#define G2_BM 32
#define G2_BK 20

__device__ __forceinline__ void gemm2_fold_body(int u, const float* __restrict__ W2,
                                                float* __restrict__ out,
                                                float* sm, int mt, int s,
                                                unsigned* s_last)
{
    float* As = sm;                 // [G2_BK][32]
    float* Bs = sm + G2_BK*G2_BM;   // [G2_BK][100]

    const float* h1sOld = g_h1s2 + (size_t)(u&1) * (BATCH*HID);

    const int tid   = threadIdx.x;
    const int m0    = mt * G2_BM;
    const int kbase = s * KC;
    const int oq    = tid % 25;
    const int rg    = tid / 25;

    float accB[8][4];
#pragma unroll
    for (int i = 0; i < 8; i++)
#pragma unroll
        for (int j = 0; j < 4; j++) accB[i][j] = 0.0f;

    for (int sub = 0; sub < KC / G2_BK; sub++) {       // 10 subtiles of 20
        const int koff = kbase + sub * G2_BK;
        __syncthreads();
        for (int idx = tid; idx < G2_BM * (G2_BK/4); idx += 128) {
            int r = idx / (G2_BK/4), f = idx % (G2_BK/4);
            float4 v = *(const float4*)(h1sOld + (size_t)(m0 + r) * HID + koff + f*4);
            As[(f*4+0)*G2_BM + r] = v.x; As[(f*4+1)*G2_BM + r] = v.y;
            As[(f*4+2)*G2_BM + r] = v.z; As[(f*4+3)*G2_BM + r] = v.w;
        }
        for (int idx = tid; idx < OUT_F * (G2_BK/4); idx += 128) {
            int o = idx / (G2_BK/4), f = idx % (G2_BK/4);
            float4 v = *(const float4*)(W2 + (size_t)o * HID + koff + f*4);
            Bs[(f*4+0)*OUT_F + o] = v.x; Bs[(f*4+1)*OUT_F + o] = v.y;
            Bs[(f*4+2)*OUT_F + o] = v.z; Bs[(f*4+3)*OUT_F + o] = v.w;
        }
        __syncthreads();

        if (rg < 4) {
#pragma unroll
            for (int kk = 0; kk < G2_BK; kk++) {
                float4 a0 = *(float4*)&As[kk*G2_BM + rg*8];
                float4 a1 = *(float4*)&As[kk*G2_BM + rg*8 + 4];
                float4 b  = *(float4*)&Bs[kk*OUT_F + oq*4];
                float a[8] = {a0.x,a0.y,a0.z,a0.w,a1.x,a1.y,a1.z,a1.w};
#pragma unroll
                for (int i = 0; i < 8; i++) {
                    accB[i][0] += a[i] * b.x; accB[i][1] += a[i] * b.y;
                    accB[i][2] += a[i] * b.z; accB[i][3] += a[i] * b.w;
                }
            }
        }
    }

    if (rg < 4) {
        float* P = g_P2 + (size_t)s * BO;
#pragma unroll
        for (int i = 0; i < 8; i++) {
            int row = m0 + rg*8 + i;
            float4 v = make_float4(accB[i][0], accB[i][1], accB[i][2], accB[i][3]);
            *(float4*)(P + (size_t)row * OUT_F + oq*4) = v;
        }
    }

    __threadfence();
    if (tid == 0) *s_last = (atomicAdd(&g_cnt2[mt], 1u) == NSLICE - 1) ? 1u : 0u;
    __syncthreads();
    if (!*s_last) return;
    if (tid == 0) g_cnt2[mt] = 0u;
    __threadfence();
    __syncthreads();   // smem reuse safety

    float* sspk = sm;  // [32][100]
    const float decv = g_dec[1];
    const float deca = g_dec[2];

    if (tid < OUT_F) {
        const int o = tid;
        for (int r = 0; r < G2_BM; r++) {
            int idx = (m0 + r) * OUT_F + o;
            float I = g_P2[idx];
            I = __fadd_rn(I, g_P2[1*BO + idx]);
            I = __fadd_rn(I, g_P2[2*BO + idx]);
            I = __fadd_rn(I, g_P2[3*BO + idx]);
            I = __fadd_rn(I, g_P2[4*BO + idx]);
            float m = g_h2m[idx] * decv * (1.0f - g_h2s[idx]) + I;
            float spk = (m >= 1.0f) ? 1.0f : 0.0f;
            g_h2m[idx] = m;
            g_h2s[idx] = spk;
            sspk[r*OUT_F + o] = spk;
        }
    }
    __syncthreads();
    for (int idx = tid; idx < G2_BM * 10; idx += 128) {
        int r = idx / 10, o = idx % 10;
        float sum = 0.0f;
#pragma unroll
        for (int i = 0; i < 10; i++) sum = __fadd_rn(sum, sspk[r*OUT_F + o*10 + i]);
        float boost = __fdiv_rn(sum, 10.0f);
        int b = m0 + r;
        out[b*10 + o] = __fadd_rn(__fmul_rn(out[b*10 + o], deca), boost);
    }
}

// ---------------------------------------------------------------------------
// Combined per-step kernel:
//   bids [0,1024)      : gemm1 slice blocks (s = bid>>8, tile = bid&255)
//   bids [1024,1184)   : gemm2(t-1) + fold
// ---------------------------------------------------------------------------
#define G1S_BLOCKS 1024
#define G2_BLOCKS  160

__global__ void __launch_bounds__(128, 5) k_step(int t, const float* __restrict__ W1,
                                                 const float* __restrict__ W2,
                                                 float* __restrict__ out)
{
    __shared__ __align__(16) float sm[SMEM_FLOATS];
    __shared__ unsigned s_last;
    int bid = blockIdx.x;
    if (bid < G1S_BLOCKS) {
        int s = bid >> 8, tile = bid & 255;
        gemm1_slice_body(t, W1, sm, tile & 15, tile >> 4, s, &s_last);
    } else if (t > 0) {
        int g = bid - G1S_BLOCKS;
        gemm2_fold_body(t - 1, W2, out, sm, g % 32, g / 32, &s_last);
    }
}

// Tail: gemm2+fold for the final step
__global__ void __launch_bounds__(128, 5) k_tail(const float* __restrict__ W2,
                                                 float* __restrict__ out)
{
    __shared__ __align__(16) float sm[SMEM_FLOATS];
    __shared__ unsigned s_last;
    int g = blockIdx.x;
    gemm2_fold_body(T_STEPS - 1, W2, out, sm, g % 32, g / 32, &s_last);
}

// ---------------------------------------------------------------------------
// Launch
// ---------------------------------------------------------------------------
extern "C" void kernel_launch(void* const* d_in, const int* in_sizes, int n_in,
                              void* d_out, int out_size)
{
    const float* x   = (const float*)d_in[0];
    const float* W1  = (const float*)d_in[1];
    const float* W2  = (const float*)d_in[2];
    const float* t0  = (const float*)d_in[3];
    const float* tv  = (const float*)d_in[4];
    const float* ta  = (const float*)d_in[5];
    float* out = (float*)d_out;
    (void)in_sizes; (void)n_in; (void)out_size;

    k_init<<<256, 256>>>(t0, tv, ta, out);
    k_spikegen<<<(TOTAL/4 + 255) / 256, 256>>>(x);

    for (int t = 0; t < T_STEPS; t++)
        k_step<<<G1S_BLOCKS + G2_BLOCKS, 128>>>(t, W1, W2, out);
    k_tail<<<G2_BLOCKS, 128>>>(W2, out);
}